// round 6
// baseline (speedup 1.0000x reference)
#include <cuda_runtime.h>
#include <cuda_fp16.h>

#define NN 100000
#define EE 1600000
#define DIN 128
#define HIDD 64
#define GG 256
#define NLAYERS 3
#define BN_EPS 1e-5f
#define NB_SCAN ((NN + 255) / 256)   // 391

// ---------------- device scratch (no allocs allowed) ----------------
__device__ __align__(16) int    g_cnt[NN];
__device__ __align__(16) int    g_fill[NN];
__device__ __align__(16) int    g_off[NN + 1];
__device__ __align__(16) int    g_bsum[NB_SCAN];
__device__ __align__(16) int    g_boff[512];
__device__ __align__(16) float  g_dinv[NN];
__device__ __align__(16) int    g_src[EE];
__device__ __align__(16) int    g_dst[EE];
__device__ __align__(16) int2   g_csr[EE];       // .x = src, .y = bits(norm)
__device__ __align__(16) int    g_batch[NN];
__device__ __align__(16) __half g_h[NN * HIDD];  // node features (fp16 storage)
__device__ __align__(16) float  g_a[NN * HIDD];  // aggregated features (fp32)
__device__ __align__(16) float  g_gsum[GG * HIDD];
__device__ __align__(16) float  g_gcnt[GG];
__device__ int g_is64;

// ---------------- dtype detection ----------------
__global__ void k_detect(const int* __restrict__ ei) {
    int nz = 0;
    for (int i = 0; i < 32; i++) nz |= ei[2 * i + 1];
    g_is64 = (nz == 0) ? 1 : 0;
}

__global__ void k_init() {
    int i = blockIdx.x * blockDim.x + threadIdx.x;
    if (i < NN) { g_cnt[i] = 0; g_fill[i] = 0; }
    if (i < GG * HIDD) g_gsum[i] = 0.f;
    if (i < GG) g_gcnt[i] = 0.f;
    if (i == 0) g_off[NN] = EE;
}

// indices -> int32, in-degree count, per-graph node count
__global__ void k_convert(const int* __restrict__ ei, const int* __restrict__ bt) {
    int i = blockIdx.x * blockDim.x + threadIdx.x;
    const bool is64 = (g_is64 != 0);
    if (i < EE) {
        int s = is64 ? ei[2 * i] : ei[i];
        int d = is64 ? ei[2 * (EE + i)] : ei[EE + i];
        g_src[i] = s;
        g_dst[i] = d;
        atomicAdd(&g_cnt[d], 1);
    }
    if (i < NN) {
        int b = is64 ? bt[2 * i] : bt[i];
        g_batch[i] = b;
        atomicAdd(&g_gcnt[b], 1.f);
    }
}

// ---------------- prefix scan (also emits dinv) ----------------
__global__ void k_scan_block() {
    __shared__ int s[256];
    int b = blockIdx.x, t = threadIdx.x, i = b * 256 + t;
    int v = (i < NN) ? g_cnt[i] : 0;
    if (i < NN) g_dinv[i] = rsqrtf((float)(v + 1));
    s[t] = v; __syncthreads();
#pragma unroll
    for (int o = 1; o < 256; o <<= 1) {
        int x = (t >= o) ? s[t - o] : 0;
        __syncthreads();
        s[t] += x;
        __syncthreads();
    }
    if (i < NN) g_off[i] = s[t] - v;
    if (t == 255) g_bsum[b] = s[255];
}

__global__ void k_scan_top() {
    __shared__ int s[512];
    int t = threadIdx.x;
    int v = (t < NB_SCAN) ? g_bsum[t] : 0;
    s[t] = v; __syncthreads();
#pragma unroll
    for (int o = 1; o < 512; o <<= 1) {
        int x = (t >= o) ? s[t - o] : 0;
        __syncthreads();
        s[t] += x;
        __syncthreads();
    }
    g_boff[t] = s[t] - v;
}

__global__ void k_scan_add() {
    int i = blockIdx.x * blockDim.x + threadIdx.x;
    if (i < NN) g_off[i] += g_boff[i >> 8];
}

__global__ void k_place() {
    int e = blockIdx.x * blockDim.x + threadIdx.x;
    if (e >= EE) return;
    int s = g_src[e], d = g_dst[e];
    float w = g_dinv[s] * g_dinv[d];
    int pos = g_off[d] + atomicAdd(&g_fill[d], 1);
    g_csr[pos] = make_int2(s, __float_as_int(w));
}

// ---------------- gather: a[i] = sum norm*h[src] + dinv^2*h[i]  (fp16 in, fp32 out)
__global__ void k_gather(const __half* __restrict__ h, float* __restrict__ a) {
    int gw = (blockIdx.x * blockDim.x + threadIdx.x) >> 5;
    int lane = threadIdx.x & 31;
    if (gw >= NN) return;
    float di = g_dinv[gw];
    float sw = di * di;
    float2 self = __half22float2(*(const __half2*)&h[(long)gw * HIDD + lane * 2]);
    float2 acc;
    acc.x = self.x * sw; acc.y = self.y * sw;
    int e = g_off[gw], end = g_off[gw + 1];
    for (; e + 1 < end; e += 2) {
        int2 m0 = g_csr[e];
        int2 m1 = g_csr[e + 1];
        float w0 = __int_as_float(m0.y), w1 = __int_as_float(m1.y);
        float2 v0 = __half22float2(*(const __half2*)&h[(long)m0.x * HIDD + lane * 2]);
        float2 v1 = __half22float2(*(const __half2*)&h[(long)m1.x * HIDD + lane * 2]);
        acc.x += w0 * v0.x + w1 * v1.x;
        acc.y += w0 * v0.y + w1 * v1.y;
    }
    if (e < end) {
        int2 m = g_csr[e];
        float w = __int_as_float(m.y);
        float2 v = __half22float2(*(const __half2*)&h[(long)m.x * HIDD + lane * 2]);
        acc.x += w * v.x;
        acc.y += w * v.y;
    }
    *(float2*)&a[(long)gw * HIDD + lane * 2] = acc;
}

// ---------------- tf32 tensor-core GEMM: C[N,64] = A[N,K] @ W[K,64] ----------
// mma.sync.m16n8k8 tf32, operands straight from GMEM (no smem staging).
// Block = 128 rows, 8 warps; warp = 16-row strip x 64 cols (8 n-tiles).
__device__ __forceinline__ unsigned f2tf(float f) {
    unsigned r;
    asm("cvt.rna.tf32.f32 %0, %1;" : "=r"(r) : "f"(f));
    return r;
}
__device__ __forceinline__ void mma_tf32(float* d, unsigned a0, unsigned a1,
                                         unsigned a2, unsigned a3,
                                         unsigned b0, unsigned b1) {
    asm("mma.sync.aligned.m16n8k8.row.col.f32.tf32.tf32.f32 "
        "{%0,%1,%2,%3}, {%4,%5,%6,%7}, {%8,%9}, {%0,%1,%2,%3};"
        : "+f"(d[0]), "+f"(d[1]), "+f"(d[2]), "+f"(d[3])
        : "r"(a0), "r"(a1), "r"(a2), "r"(a3), "r"(b0), "r"(b1));
}

template <int K, int FUSE, int POOL>
__global__ void __launch_bounds__(256) k_gemm_tc(
        const float* __restrict__ A, const float* __restrict__ W,
        const float* __restrict__ bias,
        const float* __restrict__ gamma, const float* __restrict__ beta,
        const float* __restrict__ mean, const float* __restrict__ var,
        __half* __restrict__ C) {
    __shared__ float sSC[64], sSH[64];
    const int tid = threadIdx.x;
    if (tid < 64) {
        float sc = 1.f, sh = bias[tid];
        if (FUSE) {
            sc = gamma[tid] * rsqrtf(var[tid] + BN_EPS);
            sh = (bias[tid] - mean[tid]) * sc + beta[tid];
        }
        sSC[tid] = sc; sSH[tid] = sh;
    }
    __syncthreads();

    const int warp = tid >> 5, lane = tid & 31;
    const int gid = lane >> 2, tig = lane & 3;
    const int r0 = blockIdx.x * 128 + warp * 16 + gid;  // rows r0, r0+8
    const int r1 = r0 + 8;
    const bool v0 = (r0 < NN), v1 = (r1 < NN);
    const float* A0 = A + (long)(v0 ? r0 : 0) * K;
    const float* A1 = A + (long)(v1 ? r1 : 0) * K;

    float acc[8][4];
#pragma unroll
    for (int nt = 0; nt < 8; nt++)
#pragma unroll
        for (int j = 0; j < 4; j++) acc[nt][j] = 0.f;

#pragma unroll
    for (int ks = 0; ks < K / 8; ks++) {
        const int k0 = ks * 8;
        unsigned a0 = f2tf(v0 ? A0[k0 + tig] : 0.f);
        unsigned a2 = f2tf(v0 ? A0[k0 + tig + 4] : 0.f);
        unsigned a1 = f2tf(v1 ? A1[k0 + tig] : 0.f);
        unsigned a3 = f2tf(v1 ? A1[k0 + tig + 4] : 0.f);
#pragma unroll
        for (int nt = 0; nt < 8; nt++) {
            unsigned b0 = f2tf(W[(k0 + tig) * HIDD + nt * 8 + gid]);
            unsigned b1 = f2tf(W[(k0 + tig + 4) * HIDD + nt * 8 + gid]);
            mma_tf32(acc[nt], a0, a1, a2, a3, b0, b1);
        }
    }

    const int b0g = (POOL && v0) ? g_batch[r0] : 0;
    const int b1g = (POOL && v1) ? g_batch[r1] : 0;
#pragma unroll
    for (int nt = 0; nt < 8; nt++) {
        const int c0 = nt * 8 + 2 * tig;
        float sc0 = sSC[c0], sc1 = sSC[c0 + 1];
        float sh0 = sSH[c0], sh1 = sSH[c0 + 1];
        float o00 = acc[nt][0] * sc0 + sh0;
        float o01 = acc[nt][1] * sc1 + sh1;
        float o10 = acc[nt][2] * sc0 + sh0;
        float o11 = acc[nt][3] * sc1 + sh1;
        if (FUSE) {
            o00 = fmaxf(o00, 0.f); o01 = fmaxf(o01, 0.f);
            o10 = fmaxf(o10, 0.f); o11 = fmaxf(o11, 0.f);
        }
        if (v0) {
            if (POOL) atomicAdd((float2*)&g_gsum[b0g * HIDD + c0], make_float2(o00, o01));
            else *(__half2*)&C[(long)r0 * HIDD + c0] = __floats2half2_rn(o00, o01);
        }
        if (v1) {
            if (POOL) atomicAdd((float2*)&g_gsum[b1g * HIDD + c0], make_float2(o10, o11));
            else *(__half2*)&C[(long)r1 * HIDD + c0] = __floats2half2_rn(o10, o11);
        }
    }
}

// ---------------- MLP head ----------------
__global__ void k_mlp(const float* __restrict__ W1, const float* __restrict__ b1,
                      const float* __restrict__ W2, const float* __restrict__ b2,
                      const float* __restrict__ W3, const float* __restrict__ b3,
                      float* __restrict__ out) {
    __shared__ float v[64], a1[64], a2[32];
    int g = blockIdx.x;
    int c = threadIdx.x;
    float cnt = fmaxf(g_gcnt[g], 1.f);
    v[c] = g_gsum[g * HIDD + c] / cnt;
    __syncthreads();
    float s = b1[c];
#pragma unroll
    for (int k = 0; k < 64; k++) s += v[k] * W1[k * 64 + c];
    a1[c] = fmaxf(s, 0.f);
    __syncthreads();
    if (c < 32) {
        float s2 = b2[c];
#pragma unroll
        for (int k = 0; k < 64; k++) s2 += a1[k] * W2[k * 32 + c];
        a2[c] = fmaxf(s2, 0.f);
    }
    __syncthreads();
    if (c < 32) {
        float p = a2[c] * W3[c];
#pragma unroll
        for (int o = 16; o > 0; o >>= 1) p += __shfl_down_sync(0xffffffff, p, o);
        if (c == 0) out[g] = p + b3[0];
    }
}

// ---------------- launch ----------------
extern "C" void kernel_launch(void* const* d_in, const int* in_sizes, int n_in,
                              void* d_out, int out_size) {
    const float* x      = (const float*)d_in[0];
    const int*   ei     = (const int*)d_in[1];
    const int*   bt     = (const int*)d_in[2];
    const float* W_in   = (const float*)d_in[3];
    const float* b_in   = (const float*)d_in[4];
    const float* conv_W = (const float*)d_in[5];
    const float* conv_b = (const float*)d_in[6];
    const float* gamma  = (const float*)d_in[7];
    const float* beta   = (const float*)d_in[8];
    const float* mean   = (const float*)d_in[9];
    const float* var    = (const float*)d_in[10];
    const float* W1     = (const float*)d_in[11];
    const float* b1     = (const float*)d_in[12];
    const float* W2     = (const float*)d_in[13];
    const float* b2     = (const float*)d_in[14];
    const float* W3     = (const float*)d_in[15];
    const float* b3     = (const float*)d_in[16];
    float* out = (float*)d_out;

    __half* p_h = nullptr;
    float*  p_a = nullptr;
    cudaGetSymbolAddress((void**)&p_h, g_h);
    cudaGetSymbolAddress((void**)&p_a, g_a);

    k_detect<<<1, 1>>>(ei);
    k_init<<<(NN + 255) / 256, 256>>>();
    k_convert<<<(EE + 255) / 256, 256>>>(ei, bt);
    k_scan_block<<<NB_SCAN, 256>>>();
    k_scan_top<<<1, 512>>>();
    k_scan_add<<<(NN + 255) / 256, 256>>>();
    k_place<<<(EE + 255) / 256, 256>>>();

    const int tc_blocks = (NN + 127) / 128;   // 782
    const int gather_blocks = (NN * 32 + 255) / 256;

    // h0 = fp16(x @ W_in + b_in)
    k_gemm_tc<DIN, 0, 0><<<tc_blocks, 256>>>(x, W_in, b_in,
                                             nullptr, nullptr, nullptr, nullptr, p_h);

    for (int l = 0; l < NLAYERS; l++) {
        const float* Wl = conv_W + (long)l * HIDD * HIDD;
        k_gather<<<gather_blocks, 256>>>(p_h, p_a);
        if (l < NLAYERS - 1)
            k_gemm_tc<HIDD, 1, 0><<<tc_blocks, 256>>>(p_a, Wl, conv_b + l * HIDD,
                                                      gamma + l * HIDD, beta + l * HIDD,
                                                      mean + l * HIDD, var + l * HIDD, p_h);
        else
            k_gemm_tc<HIDD, 1, 1><<<tc_blocks, 256>>>(p_a, Wl, conv_b + l * HIDD,
                                                      gamma + l * HIDD, beta + l * HIDD,
                                                      mean + l * HIDD, var + l * HIDD, p_h);
    }

    k_mlp<<<GG, 64>>>(W1, b1, W2, b2, W3, b3, out);
}

// round 7
// speedup vs baseline: 1.0048x; 1.0048x over previous
#include <cuda_runtime.h>
#include <cuda_fp16.h>

#define NN 100000
#define EE 1600000
#define DIN 128
#define HIDD 64
#define GG 256
#define NLAYERS 3
#define BN_EPS 1e-5f
#define NB_SCAN ((NN + 255) / 256)   // 391

// ---------------- device scratch (no allocs allowed) ----------------
__device__ __align__(16) int    g_cnt[NN];
__device__ __align__(16) int    g_fill[NN];
__device__ __align__(16) int    g_off[NN + 1];
__device__ __align__(16) int    g_bsum[NB_SCAN];
__device__ __align__(16) int    g_boff[512];
__device__ __align__(16) float  g_dinv[NN];
__device__ __align__(16) int    g_src[EE];
__device__ __align__(16) int    g_dst[EE];
__device__ __align__(16) int2   g_csr[EE];        // .x = src, .y = bits(norm)
__device__ __align__(16) int    g_batch[NN];
__device__ __align__(16) __half g_h[NN * HIDD];   // node features (fp16)
__device__ __align__(16) __half g_hw[NN * HIDD];  // transformed features (fp16)
__device__ __align__(16) float  g_gsum[GG * HIDD];
__device__ __align__(16) float  g_gcnt[GG];
__device__ int g_is64;

// ---------------- init (+ inline dtype detection) ----------------
__global__ void k_init(const int* __restrict__ ei) {
    int i = blockIdx.x * blockDim.x + threadIdx.x;
    if (i < NN) { g_cnt[i] = 0; g_fill[i] = 0; }
    if (i < GG * HIDD) g_gsum[i] = 0.f;
    if (i < GG) g_gcnt[i] = 0.f;
    if (i == 0) {
        g_off[NN] = EE;
        int nz = 0;
        for (int j = 0; j < 32; j++) nz |= ei[2 * j + 1];
        g_is64 = (nz == 0) ? 1 : 0;
    }
}

// indices -> int32, in-degree count, per-graph node count
__global__ void k_convert(const int* __restrict__ ei, const int* __restrict__ bt) {
    int i = blockIdx.x * blockDim.x + threadIdx.x;
    const bool is64 = (g_is64 != 0);
    if (i < EE) {
        int s = is64 ? ei[2 * i] : ei[i];
        int d = is64 ? ei[2 * (EE + i)] : ei[EE + i];
        g_src[i] = s;
        g_dst[i] = d;
        atomicAdd(&g_cnt[d], 1);
    }
    if (i < NN) {
        int b = is64 ? bt[2 * i] : bt[i];
        g_batch[i] = b;
        atomicAdd(&g_gcnt[b], 1.f);
    }
}

// ---------------- prefix scan (also emits dinv) ----------------
__global__ void k_scan_block() {
    __shared__ int s[256];
    int b = blockIdx.x, t = threadIdx.x, i = b * 256 + t;
    int v = (i < NN) ? g_cnt[i] : 0;
    if (i < NN) g_dinv[i] = rsqrtf((float)(v + 1));
    s[t] = v; __syncthreads();
#pragma unroll
    for (int o = 1; o < 256; o <<= 1) {
        int x = (t >= o) ? s[t - o] : 0;
        __syncthreads();
        s[t] += x;
        __syncthreads();
    }
    if (i < NN) g_off[i] = s[t] - v;
    if (t == 255) g_bsum[b] = s[255];
}

__global__ void k_scan_top() {
    __shared__ int s[512];
    int t = threadIdx.x;
    int v = (t < NB_SCAN) ? g_bsum[t] : 0;
    s[t] = v; __syncthreads();
#pragma unroll
    for (int o = 1; o < 512; o <<= 1) {
        int x = (t >= o) ? s[t - o] : 0;
        __syncthreads();
        s[t] += x;
        __syncthreads();
    }
    g_boff[t] = s[t] - v;
}

__global__ void k_scan_add() {
    int i = blockIdx.x * blockDim.x + threadIdx.x;
    if (i < NN) g_off[i] += g_boff[i >> 8];
}

__global__ void k_place() {
    int e = blockIdx.x * blockDim.x + threadIdx.x;
    if (e >= EE) return;
    int s = g_src[e], d = g_dst[e];
    float w = g_dinv[s] * g_dinv[d];
    int pos = g_off[d] + atomicAdd(&g_fill[d], 1);
    g_csr[pos] = make_int2(s, __float_as_int(w));
}

// ---------------- input GEMM: h0 = fp16(x[N,128] @ W_in + b_in) --------------
__global__ void k_gemm_in(const float* __restrict__ A, const float* __restrict__ W,
                          const float* __restrict__ bias, __half* __restrict__ C) {
    __shared__ float sA[32][68];
    __shared__ float sW[32][68];
    const int m0 = blockIdx.x * 64;
    const int tid = threadIdx.x;
    const int mg = tid / 16;
    const int cg = tid % 16;
    float acc[4][4];
#pragma unroll
    for (int i = 0; i < 4; i++)
#pragma unroll
        for (int j = 0; j < 4; j++) acc[i][j] = 0.f;

    for (int kb = 0; kb < DIN; kb += 32) {
        for (int t = tid; t < 64 * 32; t += 256) {
            int mm = t >> 5, kk = t & 31;
            int node = m0 + mm;
            sA[kk][mm] = (node < NN) ? A[(long)node * DIN + kb + kk] : 0.f;
        }
        for (int t = tid; t < 32 * 64; t += 256) {
            int kk = t >> 6, cc = t & 63;
            sW[kk][cc] = W[(kb + kk) * HIDD + cc];
        }
        __syncthreads();
#pragma unroll
        for (int kk = 0; kk < 32; kk++) {
            float4 aa = *(const float4*)&sA[kk][mg * 4];
            float4 ww = *(const float4*)&sW[kk][cg * 4];
            acc[0][0] += aa.x * ww.x; acc[0][1] += aa.x * ww.y; acc[0][2] += aa.x * ww.z; acc[0][3] += aa.x * ww.w;
            acc[1][0] += aa.y * ww.x; acc[1][1] += aa.y * ww.y; acc[1][2] += aa.y * ww.z; acc[1][3] += aa.y * ww.w;
            acc[2][0] += aa.z * ww.x; acc[2][1] += aa.z * ww.y; acc[2][2] += aa.z * ww.z; acc[2][3] += aa.z * ww.w;
            acc[3][0] += aa.w * ww.x; acc[3][1] += aa.w * ww.y; acc[3][2] += aa.w * ww.z; acc[3][3] += aa.w * ww.w;
        }
        __syncthreads();
    }
    float4 bv = *(const float4*)&bias[cg * 4];
#pragma unroll
    for (int i = 0; i < 4; i++) {
        int node = m0 + mg * 4 + i;
        if (node < NN) {
            __half2 q0 = __floats2half2_rn(acc[i][0] + bv.x, acc[i][1] + bv.y);
            __half2 q1 = __floats2half2_rn(acc[i][2] + bv.z, acc[i][3] + bv.w);
            __half2* p = (__half2*)&C[(long)node * HIDD + cg * 4];
            p[0] = q0; p[1] = q1;
        }
    }
}

// ---------------- layer GEMM: hw = fp16(h[N,64] @ W[64,64]), no epilogue -----
__global__ void k_gemm_h(const __half* __restrict__ A, const float* __restrict__ W,
                         __half* __restrict__ C) {
    __shared__ float sA[32][68];
    __shared__ float sW[32][68];
    const int m0 = blockIdx.x * 64;
    const int tid = threadIdx.x;
    const int mg = tid / 16;
    const int cg = tid % 16;
    float acc[4][4];
#pragma unroll
    for (int i = 0; i < 4; i++)
#pragma unroll
        for (int j = 0; j < 4; j++) acc[i][j] = 0.f;

    for (int kb = 0; kb < HIDD; kb += 32) {
        for (int t = tid; t < 64 * 16; t += 256) {   // __half2 granularity
            int mm = t >> 4, kp = t & 15;            // kp: half2 index within 32
            int node = m0 + mm;
            float2 v = (node < NN)
                ? __half22float2(*(const __half2*)&A[(long)node * HIDD + kb + kp * 2])
                : make_float2(0.f, 0.f);
            sA[kp * 2][mm] = v.x;
            sA[kp * 2 + 1][mm] = v.y;
        }
        for (int t = tid; t < 32 * 64; t += 256) {
            int kk = t >> 6, cc = t & 63;
            sW[kk][cc] = W[(kb + kk) * HIDD + cc];
        }
        __syncthreads();
#pragma unroll
        for (int kk = 0; kk < 32; kk++) {
            float4 aa = *(const float4*)&sA[kk][mg * 4];
            float4 ww = *(const float4*)&sW[kk][cg * 4];
            acc[0][0] += aa.x * ww.x; acc[0][1] += aa.x * ww.y; acc[0][2] += aa.x * ww.z; acc[0][3] += aa.x * ww.w;
            acc[1][0] += aa.y * ww.x; acc[1][1] += aa.y * ww.y; acc[1][2] += aa.y * ww.z; acc[1][3] += aa.y * ww.w;
            acc[2][0] += aa.z * ww.x; acc[2][1] += aa.z * ww.y; acc[2][2] += aa.z * ww.z; acc[2][3] += aa.z * ww.w;
            acc[3][0] += aa.w * ww.x; acc[3][1] += aa.w * ww.y; acc[3][2] += aa.w * ww.z; acc[3][3] += aa.w * ww.w;
        }
        __syncthreads();
    }
#pragma unroll
    for (int i = 0; i < 4; i++) {
        int node = m0 + mg * 4 + i;
        if (node < NN) {
            __half2 q0 = __floats2half2_rn(acc[i][0], acc[i][1]);
            __half2 q1 = __floats2half2_rn(acc[i][2], acc[i][3]);
            __half2* p = (__half2*)&C[(long)node * HIDD + cg * 4];
            p[0] = q0; p[1] = q1;
        }
    }
}

// ---------------- gather + epilogue: h = relu(BN(Agg(hw) + cb)) --------------
// warp-per-node; lane covers columns lane*2, lane*2+1.
// POOL=1: last layer, accumulate into per-graph sums instead of writing h.
template <int POOL>
__global__ void k_gather_ep(const __half* __restrict__ hw,
                            const float* __restrict__ cb,
                            const float* __restrict__ gamma,
                            const float* __restrict__ beta,
                            const float* __restrict__ mean,
                            const float* __restrict__ var,
                            __half* __restrict__ hout) {
    int gw = (blockIdx.x * blockDim.x + threadIdx.x) >> 5;
    int lane = threadIdx.x & 31;
    if (gw >= NN) return;
    float di = g_dinv[gw];
    float sw = di * di;
    float2 self = __half22float2(*(const __half2*)&hw[(long)gw * HIDD + lane * 2]);
    float2 acc;
    acc.x = self.x * sw; acc.y = self.y * sw;
    int e = g_off[gw], end = g_off[gw + 1];
    for (; e + 1 < end; e += 2) {
        int2 m0 = g_csr[e];
        int2 m1 = g_csr[e + 1];
        float w0 = __int_as_float(m0.y), w1 = __int_as_float(m1.y);
        float2 v0 = __half22float2(*(const __half2*)&hw[(long)m0.x * HIDD + lane * 2]);
        float2 v1 = __half22float2(*(const __half2*)&hw[(long)m1.x * HIDD + lane * 2]);
        acc.x += w0 * v0.x + w1 * v1.x;
        acc.y += w0 * v0.y + w1 * v1.y;
    }
    if (e < end) {
        int2 m = g_csr[e];
        float w = __int_as_float(m.y);
        float2 v = __half22float2(*(const __half2*)&hw[(long)m.x * HIDD + lane * 2]);
        acc.x += w * v.x;
        acc.y += w * v.y;
    }
    // epilogue: out = acc*sc + sh, sc = gamma*rsqrt(var+eps), sh = (cb-mean)*sc+beta
    int c0 = lane * 2, c1 = c0 + 1;
    float sc0 = gamma[c0] * rsqrtf(var[c0] + BN_EPS);
    float sc1 = gamma[c1] * rsqrtf(var[c1] + BN_EPS);
    float sh0 = (cb[c0] - mean[c0]) * sc0 + beta[c0];
    float sh1 = (cb[c1] - mean[c1]) * sc1 + beta[c1];
    float o0 = fmaxf(acc.x * sc0 + sh0, 0.f);
    float o1 = fmaxf(acc.y * sc1 + sh1, 0.f);
    if (POOL) {
        int b = g_batch[gw];
        atomicAdd((float2*)&g_gsum[b * HIDD + c0], make_float2(o0, o1));
    } else {
        *(__half2*)&hout[(long)gw * HIDD + c0] = __floats2half2_rn(o0, o1);
    }
}

// ---------------- MLP head ----------------
__global__ void k_mlp(const float* __restrict__ W1, const float* __restrict__ b1,
                      const float* __restrict__ W2, const float* __restrict__ b2,
                      const float* __restrict__ W3, const float* __restrict__ b3,
                      float* __restrict__ out) {
    __shared__ float v[64], a1[64], a2[32];
    int g = blockIdx.x;
    int c = threadIdx.x;
    float cnt = fmaxf(g_gcnt[g], 1.f);
    v[c] = g_gsum[g * HIDD + c] / cnt;
    __syncthreads();
    float s = b1[c];
#pragma unroll
    for (int k = 0; k < 64; k++) s += v[k] * W1[k * 64 + c];
    a1[c] = fmaxf(s, 0.f);
    __syncthreads();
    if (c < 32) {
        float s2 = b2[c];
#pragma unroll
        for (int k = 0; k < 64; k++) s2 += a1[k] * W2[k * 32 + c];
        a2[c] = fmaxf(s2, 0.f);
    }
    __syncthreads();
    if (c < 32) {
        float p = a2[c] * W3[c];
#pragma unroll
        for (int o = 16; o > 0; o >>= 1) p += __shfl_down_sync(0xffffffff, p, o);
        if (c == 0) out[g] = p + b3[0];
    }
}

// ---------------- launch ----------------
extern "C" void kernel_launch(void* const* d_in, const int* in_sizes, int n_in,
                              void* d_out, int out_size) {
    const float* x      = (const float*)d_in[0];
    const int*   ei     = (const int*)d_in[1];
    const int*   bt     = (const int*)d_in[2];
    const float* W_in   = (const float*)d_in[3];
    const float* b_in   = (const float*)d_in[4];
    const float* conv_W = (const float*)d_in[5];
    const float* conv_b = (const float*)d_in[6];
    const float* gamma  = (const float*)d_in[7];
    const float* beta   = (const float*)d_in[8];
    const float* mean   = (const float*)d_in[9];
    const float* var    = (const float*)d_in[10];
    const float* W1     = (const float*)d_in[11];
    const float* b1     = (const float*)d_in[12];
    const float* W2     = (const float*)d_in[13];
    const float* b2     = (const float*)d_in[14];
    const float* W3     = (const float*)d_in[15];
    const float* b3     = (const float*)d_in[16];
    float* out = (float*)d_out;

    __half *p_h = nullptr, *p_hw = nullptr;
    cudaGetSymbolAddress((void**)&p_h, g_h);
    cudaGetSymbolAddress((void**)&p_hw, g_hw);

    k_init<<<(NN + 255) / 256, 256>>>(ei);
    k_convert<<<(EE + 255) / 256, 256>>>(ei, bt);
    k_scan_block<<<NB_SCAN, 256>>>();
    k_scan_top<<<1, 512>>>();
    k_scan_add<<<(NN + 255) / 256, 256>>>();
    k_place<<<(EE + 255) / 256, 256>>>();

    const int gemm_blocks = (NN + 63) / 64;
    const int gather_blocks = (NN * 32 + 255) / 256;

    k_gemm_in<<<gemm_blocks, 256>>>(x, W_in, b_in, p_h);

    for (int l = 0; l < NLAYERS; l++) {
        const float* Wl = conv_W + (long)l * HIDD * HIDD;
        k_gemm_h<<<gemm_blocks, 256>>>(p_h, Wl, p_hw);
        if (l < NLAYERS - 1)
            k_gather_ep<0><<<gather_blocks, 256>>>(p_hw, conv_b + l * HIDD,
                                                   gamma + l * HIDD, beta + l * HIDD,
                                                   mean + l * HIDD, var + l * HIDD, p_h);
        else
            k_gather_ep<1><<<gather_blocks, 256>>>(p_hw, conv_b + l * HIDD,
                                                   gamma + l * HIDD, beta + l * HIDD,
                                                   mean + l * HIDD, var + l * HIDD, p_h);
    }

    k_mlp<<<GG, 64>>>(W1, b1, W2, b2, W3, b3, out);
}

// round 8
// speedup vs baseline: 1.1815x; 1.1759x over previous
#include <cuda_runtime.h>
#include <cuda_fp16.h>

#define NN 100000
#define EE 1600000
#define DIN 128
#define HIDD 64
#define GG 256
#define NLAYERS 3
#define BN_EPS 1e-5f
#define NB_SCAN ((NN + 255) / 256)   // 391

// ---------------- device scratch (no allocs allowed) ----------------
__device__ __align__(16) int    g_cnt[NN];
__device__ __align__(16) int    g_fill[NN];
__device__ __align__(16) int    g_off[NN + 1];
__device__ __align__(16) int    g_bsum[NB_SCAN];
__device__ __align__(16) int    g_boff[512];
__device__ __align__(16) float  g_dinv[NN];
__device__ __align__(16) int2   g_csr[EE];        // .x = src, .y = bits(norm)
__device__ __align__(16) int    g_batch[NN];
__device__ __align__(16) __half g_h[NN * HIDD];   // node features (fp16)
__device__ __align__(16) __half g_hw[NN * HIDD];  // transformed features (fp16)
__device__ __align__(16) float  g_gsum[GG * HIDD];
__device__ __align__(16) float  g_gcnt[GG];
__device__ int g_is64;

// ---------------- init (+ inline dtype detection) ----------------
__global__ void k_init(const int* __restrict__ ei) {
    int i = blockIdx.x * blockDim.x + threadIdx.x;
    if (i < NN) { g_cnt[i] = 0; g_fill[i] = 0; }
    if (i < GG * HIDD) g_gsum[i] = 0.f;
    if (i < GG) g_gcnt[i] = 0.f;
    if (i == 0) {
        g_off[NN] = EE;
        int nz = 0;
        for (int j = 0; j < 32; j++) nz |= ei[2 * j + 1];
        g_is64 = (nz == 0) ? 1 : 0;
    }
}

// in-degree count + batch conversion + per-graph node count
__global__ void k_convert(const int* __restrict__ ei, const int* __restrict__ bt) {
    int i = blockIdx.x * blockDim.x + threadIdx.x;
    const bool is64 = (g_is64 != 0);
    if (i < EE) {
        int d = is64 ? ei[2 * (EE + i)] : ei[EE + i];
        atomicAdd(&g_cnt[d], 1);
    }
    if (i < NN) {
        int b = is64 ? bt[2 * i] : bt[i];
        g_batch[i] = b;
        atomicAdd(&g_gcnt[b], 1.f);
    }
}

// ---------------- prefix scan (also emits dinv) ----------------
__global__ void k_scan_block() {
    __shared__ int s[256];
    int b = blockIdx.x, t = threadIdx.x, i = b * 256 + t;
    int v = (i < NN) ? g_cnt[i] : 0;
    if (i < NN) g_dinv[i] = rsqrtf((float)(v + 1));
    s[t] = v; __syncthreads();
#pragma unroll
    for (int o = 1; o < 256; o <<= 1) {
        int x = (t >= o) ? s[t - o] : 0;
        __syncthreads();
        s[t] += x;
        __syncthreads();
    }
    if (i < NN) g_off[i] = s[t] - v;
    if (t == 255) g_bsum[b] = s[255];
}

__global__ void k_scan_top() {
    __shared__ int s[512];
    int t = threadIdx.x;
    int v = (t < NB_SCAN) ? g_bsum[t] : 0;
    s[t] = v; __syncthreads();
#pragma unroll
    for (int o = 1; o < 512; o <<= 1) {
        int x = (t >= o) ? s[t - o] : 0;
        __syncthreads();
        s[t] += x;
        __syncthreads();
    }
    g_boff[t] = s[t] - v;
}

__global__ void k_scan_add() {
    int i = blockIdx.x * blockDim.x + threadIdx.x;
    if (i < NN) g_off[i] += g_boff[i >> 8];
}

// place edges into CSR, reading edge_index directly
__global__ void k_place(const int* __restrict__ ei) {
    int e = blockIdx.x * blockDim.x + threadIdx.x;
    if (e >= EE) return;
    const bool is64 = (g_is64 != 0);
    int s = is64 ? ei[2 * e] : ei[e];
    int d = is64 ? ei[2 * (EE + e)] : ei[EE + e];
    float w = g_dinv[s] * g_dinv[d];
    int pos = g_off[d] + atomicAdd(&g_fill[d], 1);
    g_csr[pos] = make_int2(s, __float_as_int(w));
}

// ---------------- HMMA m16n8k16 (fp16 x fp16 -> fp32) ----------------
__device__ __forceinline__ void hmma(float* c, unsigned a0, unsigned a1,
                                     unsigned a2, unsigned a3,
                                     unsigned b0, unsigned b1) {
    asm("mma.sync.aligned.m16n8k16.row.col.f32.f16.f16.f32 "
        "{%0,%1,%2,%3}, {%4,%5,%6,%7}, {%8,%9}, {%0,%1,%2,%3};"
        : "+f"(c[0]), "+f"(c[1]), "+f"(c[2]), "+f"(c[3])
        : "r"(a0), "r"(a1), "r"(a2), "r"(a3), "r"(b0), "r"(b1));
}

// ---------------- input GEMM (tensor core): h0 = fp16(x @ W_in + b_in) -------
// Block: 128 rows, 8 warps; warp = 16 rows x 64 cols. K=128 staged in 2 halves.
__global__ void __launch_bounds__(256) k_gemm_in_mma(
        const float* __restrict__ x, const float* __restrict__ W,
        const float* __restrict__ bias, __half* __restrict__ C) {
    __shared__ __half sA[128][72];    // A chunk: 128 rows x 64 k
    __shared__ __half sB[64][136];    // W transposed: [n][k], full K=128
    const int tid = threadIdx.x;
    const int warp = tid >> 5, lane = tid & 31;
    const int g = lane >> 2, tq = lane & 3;
    const int base = blockIdx.x * 128;

    for (int t = tid; t < DIN * HIDD; t += 256) {
        int k = t >> 6, n = t & 63;
        sB[n][k] = __float2half(W[t]);
    }

    float c[8][4];
#pragma unroll
    for (int nt = 0; nt < 8; nt++)
#pragma unroll
        for (int j = 0; j < 4; j++) c[nt][j] = 0.f;

#pragma unroll
    for (int half = 0; half < 2; half++) {
        __syncthreads();
        for (int t = tid; t < 128 * 32; t += 256) {
            int row = t >> 5, p = t & 31;
            int node = base + row;
            float2 v = (node < NN)
                ? *(const float2*)&x[(long)node * DIN + half * 64 + p * 2]
                : make_float2(0.f, 0.f);
            *(__half2*)&sA[row][p * 2] = __floats2half2_rn(v.x, v.y);
        }
        __syncthreads();
#pragma unroll
        for (int ks = 0; ks < 4; ks++) {
            int k0 = ks * 16 + tq * 2;
            unsigned a0 = *(const unsigned*)&sA[warp * 16 + g][k0];
            unsigned a1 = *(const unsigned*)&sA[warp * 16 + g + 8][k0];
            unsigned a2 = *(const unsigned*)&sA[warp * 16 + g][k0 + 8];
            unsigned a3 = *(const unsigned*)&sA[warp * 16 + g + 8][k0 + 8];
#pragma unroll
            for (int nt = 0; nt < 8; nt++) {
                unsigned b0 = *(const unsigned*)&sB[nt * 8 + g][half * 64 + k0];
                unsigned b1 = *(const unsigned*)&sB[nt * 8 + g][half * 64 + k0 + 8];
                hmma(c[nt], a0, a1, a2, a3, b0, b1);
            }
        }
    }

    const int r0 = base + warp * 16 + g;
    const int r1 = r0 + 8;
#pragma unroll
    for (int nt = 0; nt < 8; nt++) {
        int c0 = nt * 8 + tq * 2;
        float bv0 = bias[c0], bv1 = bias[c0 + 1];
        if (r0 < NN)
            *(__half2*)&C[(long)r0 * HIDD + c0] =
                __floats2half2_rn(c[nt][0] + bv0, c[nt][1] + bv1);
        if (r1 < NN)
            *(__half2*)&C[(long)r1 * HIDD + c0] =
                __floats2half2_rn(c[nt][2] + bv0, c[nt][3] + bv1);
    }
}

// ---------------- layer GEMM (tensor core): hw = fp16(h @ W), K=64 -----------
// A fragments straight from gmem (fp16 rows), W staged transposed in smem.
__global__ void __launch_bounds__(256) k_gemm_h_mma(
        const __half* __restrict__ A, const float* __restrict__ W,
        __half* __restrict__ C) {
    __shared__ __half sB[64][72];
    const int tid = threadIdx.x;
    const int warp = tid >> 5, lane = tid & 31;
    const int g = lane >> 2, tq = lane & 3;

    for (int t = tid; t < HIDD * HIDD; t += 256) {
        int k = t >> 6, n = t & 63;
        sB[n][k] = __float2half(W[t]);
    }
    __syncthreads();

    const int r0 = blockIdx.x * 128 + warp * 16 + g;
    const int r1 = r0 + 8;
    const bool v0 = (r0 < NN), v1 = (r1 < NN);
    const __half* A0 = A + (long)(v0 ? r0 : 0) * HIDD;
    const __half* A1 = A + (long)(v1 ? r1 : 0) * HIDD;

    float c[8][4];
#pragma unroll
    for (int nt = 0; nt < 8; nt++)
#pragma unroll
        for (int j = 0; j < 4; j++) c[nt][j] = 0.f;

#pragma unroll
    for (int ks = 0; ks < 4; ks++) {
        int k0 = ks * 16 + tq * 2;
        unsigned a0 = *(const unsigned*)&A0[k0];
        unsigned a1 = *(const unsigned*)&A1[k0];
        unsigned a2 = *(const unsigned*)&A0[k0 + 8];
        unsigned a3 = *(const unsigned*)&A1[k0 + 8];
#pragma unroll
        for (int nt = 0; nt < 8; nt++) {
            unsigned b0 = *(const unsigned*)&sB[nt * 8 + g][k0];
            unsigned b1 = *(const unsigned*)&sB[nt * 8 + g][k0 + 8];
            hmma(c[nt], a0, a1, a2, a3, b0, b1);
        }
    }

#pragma unroll
    for (int nt = 0; nt < 8; nt++) {
        int c0 = nt * 8 + tq * 2;
        if (v0) *(__half2*)&C[(long)r0 * HIDD + c0] = __floats2half2_rn(c[nt][0], c[nt][1]);
        if (v1) *(__half2*)&C[(long)r1 * HIDD + c0] = __floats2half2_rn(c[nt][2], c[nt][3]);
    }
}

// ---------------- gather + epilogue: h = relu(BN(Agg(hw) + cb)) --------------
// warp-per-node; POOL=1: accumulate into per-graph sums.
template <int POOL>
__global__ void k_gather_ep(const __half* __restrict__ hw,
                            const float* __restrict__ cb,
                            const float* __restrict__ gamma,
                            const float* __restrict__ beta,
                            const float* __restrict__ mean,
                            const float* __restrict__ var,
                            __half* __restrict__ hout) {
    int gw = (blockIdx.x * blockDim.x + threadIdx.x) >> 5;
    int lane = threadIdx.x & 31;
    if (gw >= NN) return;
    float di = g_dinv[gw];
    float sw = di * di;
    float2 self = __half22float2(*(const __half2*)&hw[(long)gw * HIDD + lane * 2]);
    float2 acc;
    acc.x = self.x * sw; acc.y = self.y * sw;
    int e = g_off[gw], end = g_off[gw + 1];
    for (; e + 1 < end; e += 2) {
        int2 m0 = g_csr[e];
        int2 m1 = g_csr[e + 1];
        float w0 = __int_as_float(m0.y), w1 = __int_as_float(m1.y);
        float2 v0 = __half22float2(*(const __half2*)&hw[(long)m0.x * HIDD + lane * 2]);
        float2 v1 = __half22float2(*(const __half2*)&hw[(long)m1.x * HIDD + lane * 2]);
        acc.x += w0 * v0.x + w1 * v1.x;
        acc.y += w0 * v0.y + w1 * v1.y;
    }
    if (e < end) {
        int2 m = g_csr[e];
        float w = __int_as_float(m.y);
        float2 v = __half22float2(*(const __half2*)&hw[(long)m.x * HIDD + lane * 2]);
        acc.x += w * v.x;
        acc.y += w * v.y;
    }
    int c0 = lane * 2, c1 = c0 + 1;
    float sc0 = gamma[c0] * rsqrtf(var[c0] + BN_EPS);
    float sc1 = gamma[c1] * rsqrtf(var[c1] + BN_EPS);
    float sh0 = (cb[c0] - mean[c0]) * sc0 + beta[c0];
    float sh1 = (cb[c1] - mean[c1]) * sc1 + beta[c1];
    float o0 = fmaxf(acc.x * sc0 + sh0, 0.f);
    float o1 = fmaxf(acc.y * sc1 + sh1, 0.f);
    if (POOL) {
        int b = g_batch[gw];
        atomicAdd((float2*)&g_gsum[b * HIDD + c0], make_float2(o0, o1));
    } else {
        *(__half2*)&hout[(long)gw * HIDD + c0] = __floats2half2_rn(o0, o1);
    }
}

// ---------------- MLP head ----------------
__global__ void k_mlp(const float* __restrict__ W1, const float* __restrict__ b1,
                      const float* __restrict__ W2, const float* __restrict__ b2,
                      const float* __restrict__ W3, const float* __restrict__ b3,
                      float* __restrict__ out) {
    __shared__ float v[64], a1[64], a2[32];
    int g = blockIdx.x;
    int c = threadIdx.x;
    float cnt = fmaxf(g_gcnt[g], 1.f);
    v[c] = g_gsum[g * HIDD + c] / cnt;
    __syncthreads();
    float s = b1[c];
#pragma unroll
    for (int k = 0; k < 64; k++) s += v[k] * W1[k * 64 + c];
    a1[c] = fmaxf(s, 0.f);
    __syncthreads();
    if (c < 32) {
        float s2 = b2[c];
#pragma unroll
        for (int k = 0; k < 64; k++) s2 += a1[k] * W2[k * 32 + c];
        a2[c] = fmaxf(s2, 0.f);
    }
    __syncthreads();
    if (c < 32) {
        float p = a2[c] * W3[c];
#pragma unroll
        for (int o = 16; o > 0; o >>= 1) p += __shfl_down_sync(0xffffffff, p, o);
        if (c == 0) out[g] = p + b3[0];
    }
}

// ---------------- launch ----------------
extern "C" void kernel_launch(void* const* d_in, const int* in_sizes, int n_in,
                              void* d_out, int out_size) {
    const float* x      = (const float*)d_in[0];
    const int*   ei     = (const int*)d_in[1];
    const int*   bt     = (const int*)d_in[2];
    const float* W_in   = (const float*)d_in[3];
    const float* b_in   = (const float*)d_in[4];
    const float* conv_W = (const float*)d_in[5];
    const float* conv_b = (const float*)d_in[6];
    const float* gamma  = (const float*)d_in[7];
    const float* beta   = (const float*)d_in[8];
    const float* mean   = (const float*)d_in[9];
    const float* var    = (const float*)d_in[10];
    const float* W1     = (const float*)d_in[11];
    const float* b1     = (const float*)d_in[12];
    const float* W2     = (const float*)d_in[13];
    const float* b2     = (const float*)d_in[14];
    const float* W3     = (const float*)d_in[15];
    const float* b3     = (const float*)d_in[16];
    float* out = (float*)d_out;

    __half *p_h = nullptr, *p_hw = nullptr;
    cudaGetSymbolAddress((void**)&p_h, g_h);
    cudaGetSymbolAddress((void**)&p_hw, g_hw);

    k_init<<<(NN + 255) / 256, 256>>>(ei);
    k_convert<<<(EE + 255) / 256, 256>>>(ei, bt);
    k_scan_block<<<NB_SCAN, 256>>>();
    k_scan_top<<<1, 512>>>();
    k_scan_add<<<(NN + 255) / 256, 256>>>();
    k_place<<<(EE + 255) / 256, 256>>>(ei);

    const int mma_blocks = (NN + 127) / 128;   // 782
    const int gather_blocks = (NN * 32 + 255) / 256;

    k_gemm_in_mma<<<mma_blocks, 256>>>(x, W_in, b_in, p_h);

    for (int l = 0; l < NLAYERS; l++) {
        const float* Wl = conv_W + (long)l * HIDD * HIDD;
        k_gemm_h_mma<<<mma_blocks, 256>>>(p_h, Wl, p_hw);
        if (l < NLAYERS - 1)
            k_gather_ep<0><<<gather_blocks, 256>>>(p_hw, conv_b + l * HIDD,
                                                   gamma + l * HIDD, beta + l * HIDD,
                                                   mean + l * HIDD, var + l * HIDD, p_h);
        else
            k_gather_ep<1><<<gather_blocks, 256>>>(p_hw, conv_b + l * HIDD,
                                                   gamma + l * HIDD, beta + l * HIDD,
                                                   mean + l * HIDD, var + l * HIDD, p_h);
    }

    k_mlp<<<GG, 64>>>(W1, b1, W2, b2, W3, b3, out);
}